// round 1
// baseline (speedup 1.0000x reference)
#include <cuda_runtime.h>
#include <cuda_bf16.h>

// SAME-padded stride-1 3x3 conv, NHWC, fp32.
// x: [32,56,56,128], w: [3,3,128,256], b: [256] -> out: [32,56,56,256]
//
// Implicit GEMM: M = B*H*W = 100352 pixels, N = 256, K = 9*128.
// CTA tile: BM=128 pixels x BN=128 couts, K-chunks of BK=32 cin, looping
// over the 9 (kh,kw) taps with per-pixel halo masking (zero fill).
// Thread micro-tile: 8x8 (256 threads = 16x16 layout).

#define CONV_B    32
#define CONV_H    56
#define CONV_W    56
#define CONV_CIN  128
#define CONV_COUT 256

#define BM 128
#define BN 128
#define BK 32
#define TM 8
#define TN 8

__global__ __launch_bounds__(256)
void conv3x3_ffma_kernel(const float* __restrict__ x,
                         const float* __restrict__ w,
                         const float* __restrict__ bias,
                         float* __restrict__ out)
{
    // A stored transposed [k][pixel] so compute-phase reads are LDS.128.
    __shared__ float As[BK][BM];
    __shared__ float Bs[BK][BN];

    const int tid = threadIdx.x;
    const int bn  = blockIdx.x;   // 0..1   (cout block)
    const int bm  = blockIdx.y;   // 0..783 (pixel block)

    // ---- loader-side coordinates (2 threads per pixel, 16 cin each) ----
    const int lpix = tid >> 1;          // 0..127 pixel within tile
    const int lc   = (tid & 1) * 16;    // cin sub-offset 0 or 16
    const int p    = bm * BM + lpix;    // global pixel (always < 100352)
    const int n    = p / (CONV_H * CONV_W);
    const int hw   = p % (CONV_H * CONV_W);
    const int ph   = hw / CONV_W;
    const int pw   = hw % CONV_W;

    // ---- compute-side coordinates ----
    const int tx = tid & 15;   // N dim
    const int ty = tid >> 4;   // M dim

    float acc[TM][TN];
    #pragma unroll
    for (int i = 0; i < TM; ++i)
        #pragma unroll
        for (int j = 0; j < TN; ++j)
            acc[i][j] = 0.0f;

    for (int kh = 0; kh < 3; ++kh) {
        const int hh = ph + kh - 1;
        const bool hok = ((unsigned)hh < (unsigned)CONV_H);
        for (int kw = 0; kw < 3; ++kw) {
            const int ww = pw + kw - 1;
            const bool ok = hok && ((unsigned)ww < (unsigned)CONV_W);
            // base of this pixel's shifted input vector (only deref'd if ok)
            const float* srcbase =
                x + ((size_t)((n * CONV_H + hh) * CONV_W + ww)) * CONV_CIN + lc;
            const float* wbase =
                w + ((size_t)(kh * 3 + kw) * CONV_CIN) * CONV_COUT + bn * BN;

            for (int c0 = 0; c0 < CONV_CIN; c0 += BK) {
                __syncthreads();  // previous tile fully consumed

                // ---- load A tile: 128 pixels x 32 cin (transposed store) ----
                #pragma unroll
                for (int i = 0; i < 4; ++i) {
                    float4 v = make_float4(0.f, 0.f, 0.f, 0.f);
                    if (ok) v = *(const float4*)(srcbase + c0 + i * 4);
                    const int cl = lc + i * 4;
                    As[cl + 0][lpix] = v.x;
                    As[cl + 1][lpix] = v.y;
                    As[cl + 2][lpix] = v.z;
                    As[cl + 3][lpix] = v.w;
                }

                // ---- load B tile: 32 cin x 128 cout ----
                #pragma unroll
                for (int i = 0; i < 4; ++i) {
                    const int f   = tid + i * 256;   // 0..1023 float4 slots
                    const int row = f >> 5;          // cin row 0..31
                    const int c4  = f & 31;          // float4 col 0..31
                    float4 v = *(const float4*)(wbase +
                                 (size_t)(c0 + row) * CONV_COUT + c4 * 4);
                    *(float4*)&Bs[row][c4 * 4] = v;
                }

                __syncthreads();

                // ---- compute: 32 k-steps of 8x8 FMA ----
                #pragma unroll
                for (int k = 0; k < BK; ++k) {
                    float4 a0 = *(const float4*)&As[k][ty * TM];
                    float4 a1 = *(const float4*)&As[k][ty * TM + 4];
                    float4 b0 = *(const float4*)&Bs[k][tx * TN];
                    float4 b1 = *(const float4*)&Bs[k][tx * TN + 4];
                    const float a[TM] = {a0.x, a0.y, a0.z, a0.w,
                                         a1.x, a1.y, a1.z, a1.w};
                    const float bb[TN] = {b0.x, b0.y, b0.z, b0.w,
                                          b1.x, b1.y, b1.z, b1.w};
                    #pragma unroll
                    for (int i = 0; i < TM; ++i)
                        #pragma unroll
                        for (int j = 0; j < TN; ++j)
                            acc[i][j] = fmaf(a[i], bb[j], acc[i][j]);
                }
            }
        }
    }

    // ---- epilogue: bias + store ----
    float bv[TN];
    #pragma unroll
    for (int j = 0; j < TN; ++j)
        bv[j] = bias[bn * BN + tx * TN + j];

    #pragma unroll
    for (int i = 0; i < TM; ++i) {
        const int pi = bm * BM + ty * TM + i;       // global pixel
        float* orow = out + (size_t)pi * CONV_COUT + bn * BN + tx * TN;
        float4 o0, o1;
        o0.x = acc[i][0] + bv[0];
        o0.y = acc[i][1] + bv[1];
        o0.z = acc[i][2] + bv[2];
        o0.w = acc[i][3] + bv[3];
        o1.x = acc[i][4] + bv[4];
        o1.y = acc[i][5] + bv[5];
        o1.z = acc[i][6] + bv[6];
        o1.w = acc[i][7] + bv[7];
        *(float4*)(orow)     = o0;
        *(float4*)(orow + 4) = o1;
    }
}

extern "C" void kernel_launch(void* const* d_in, const int* in_sizes, int n_in,
                              void* d_out, int out_size)
{
    const float* x    = (const float*)d_in[0];  // [32,56,56,128]
    const float* w    = (const float*)d_in[1];  // [3,3,128,256]
    const float* bias = (const float*)d_in[2];  // [256]
    float* out = (float*)d_out;                 // [32,56,56,256]

    // M = 100352 pixels = 784 tiles of 128; N = 256 = 2 tiles of 128.
    dim3 grid(CONV_COUT / BN, (CONV_B * CONV_H * CONV_W) / BM);
    conv3x3_ffma_kernel<<<grid, 256>>>(x, w, bias, out);
}

// round 3
// speedup vs baseline: 2.7903x; 2.7903x over previous
#include <cuda_runtime.h>
#include <cstdint>

// SAME-padded stride-1 3x3 conv, NHWC fp32, via mma.sync tf32 implicit GEMM.
// x: [32,56,56,128], w: [3,3,128,256], b: [256] -> out: [32,56,56,256]
// M = 100352 pixels, N = 256, K = 9*128 = 1152.

#define CB    32
#define CH    56
#define CW    56
#define CCIN  128
#define CCOUT 256
#define NPIX  (CB * CH * CW)      // 100352
#define KTOT  1152
#define NCHUNKS 36                // 9 taps * 4 cin-chunks of 32

#define BM 256
#define BN 128
#define BK 32
#define NTHREADS 512              // 16 warps, 4(M) x 4(N)
#define STAGES 3

// smem strides in 4-byte words (padded for conflict-free fragment loads)
#define A_ROW 36                  // 32 k + 4 pad
#define B_ROW 132                 // 128 n + 4 pad
#define A_STAGE_W (BM * A_ROW)    // 9216 words  (36864 B)
#define B_STAGE_W (BK * B_ROW)    // 4224 words  (16896 B)
#define SMEM_BYTES (STAGES * (A_STAGE_W + B_STAGE_W) * 4)   // 161280

// ---------------- scratch: tf32(rne)-rounded copies ----------------
__device__ __align__(1024) float g_x_t[NPIX * CCIN];    // same layout as x
__device__ __align__(1024) float g_w_t[KTOT * CCOUT];   // same layout as w

// ---------------- helpers ----------------
__device__ __forceinline__ uint32_t smem_u32(const void* p) {
    uint32_t a;
    asm("{ .reg .u64 t; cvta.to.shared.u64 t, %1; cvt.u32.u64 %0, t; }"
        : "=r"(a) : "l"(p));
    return a;
}

__device__ __forceinline__ void cp16(uint32_t dst, const void* src, uint32_t srcsz) {
    asm volatile("cp.async.cg.shared.global [%0], [%1], 16, %2;"
                 :: "r"(dst), "l"(src), "r"(srcsz) : "memory");
}
#define CP_COMMIT() asm volatile("cp.async.commit_group;" ::: "memory")
#define CP_WAIT1()  asm volatile("cp.async.wait_group 1;" ::: "memory")

__device__ __forceinline__ void mma_tf32(float c[4], const uint32_t a[4],
                                         const uint32_t b[2]) {
    asm volatile(
        "mma.sync.aligned.m16n8k8.row.col.f32.tf32.tf32.f32 "
        "{%0,%1,%2,%3}, {%4,%5,%6,%7}, {%8,%9}, {%0,%1,%2,%3};"
        : "+f"(c[0]), "+f"(c[1]), "+f"(c[2]), "+f"(c[3])
        : "r"(a[0]), "r"(a[1]), "r"(a[2]), "r"(a[3]),
          "r"(b[0]), "r"(b[1]));
}

__device__ __forceinline__ float rna_tf32(float v) {
    uint32_t r;
    asm("cvt.rna.tf32.f32 %0, %1;" : "=r"(r) : "f"(v));
    return __uint_as_float(r);
}

// ---------------- pre-kernels: fp32 -> tf32(rne) rounding ----------------
__global__ void k_cvt(const float* __restrict__ in, float* __restrict__ outp,
                      int total4) {
    const float4* xi = (const float4*)in;
    float4* yo = (float4*)outp;
    for (int i = blockIdx.x * blockDim.x + threadIdx.x; i < total4;
         i += gridDim.x * blockDim.x) {
        float4 v = xi[i];
        v.x = rna_tf32(v.x); v.y = rna_tf32(v.y);
        v.z = rna_tf32(v.z); v.w = rna_tf32(v.w);
        yo[i] = v;
    }
}

// ---------------- main kernel ----------------
__global__ __launch_bounds__(NTHREADS, 1)
void conv_mma(const float* __restrict__ xt, const float* __restrict__ wt,
              const float* __restrict__ bias, float* __restrict__ out)
{
    extern __shared__ float smem[];
    const uint32_t sm_a = smem_u32(smem);                       // A stages (bytes)
    const uint32_t sm_b = sm_a + STAGES * A_STAGE_W * 4;        // B stages

    const int tid  = threadIdx.x;
    const int wid  = tid >> 5;
    const int lane = tid & 31;
    const int lr   = lane >> 2;    // 0..7
    const int lc   = lane & 3;     // 0..3
    const int bn = blockIdx.x;     // 0..1
    const int bm = blockIdx.y;     // 0..391

    // ---- A loader coords: 4 pixels per thread (pixel-local = tid>>3 + 64q) ----
    const int s7 = tid & 7;        // 16B segment within 128B cin-chunk
    int ah[4], aw[4];
    uint32_t abase[4];             // float offset of (n,0,0,0)
    #pragma unroll
    for (int q = 0; q < 4; ++q) {
        int pix = bm * BM + (tid >> 3) + q * 64;
        int n   = pix / (CH * CW);
        int hw  = pix % (CH * CW);
        ah[q] = hw / CW;
        aw[q] = hw % CW;
        abase[q] = (uint32_t)n * (CH * CW * CCIN);
    }
    // ---- B loader coords: 2 rows per thread ----
    const int brow = tid >> 5;     // 0..15 (and +16)
    const int bsc  = tid & 31;     // 16B segment within 512B row

    // accumulators: warp tile 64x32 -> 4 m-tiles x 4 n-tiles x 4 regs
    float acc[4][4][4];
    #pragma unroll
    for (int t = 0; t < 4; ++t)
        #pragma unroll
        for (int u = 0; u < 4; ++u)
            #pragma unroll
            for (int r = 0; r < 4; ++r)
                acc[t][u][r] = 0.0f;

    const int warp_m = wid >> 2;   // 0..3
    const int warp_n = wid & 3;    // 0..3

    // ---------------- load issuer ----------------
    auto load_chunk = [&](int i, int stage) {
        const int tap = i >> 2, csub = i & 3;
        const int dh = tap / 3 - 1, dw = tap % 3 - 1;
        const uint32_t a_st = sm_a + stage * A_STAGE_W * 4;
        const uint32_t b_st = sm_b + stage * B_STAGE_W * 4;
        #pragma unroll
        for (int q = 0; q < 4; ++q) {
            const int h2 = ah[q] + dh, w2 = aw[q] + dw;
            const bool ok = ((unsigned)h2 < CH) && ((unsigned)w2 < CW);
            uint32_t off = ok ? (abase[q] + (uint32_t)(h2 * CW + w2) * CCIN
                                 + csub * 32 + s7 * 4)
                              : 0u;
            const uint32_t dst = a_st + (uint32_t)((tid >> 3) + q * 64) * (A_ROW * 4)
                               + s7 * 16;
            cp16(dst, xt + off, ok ? 16u : 0u);
        }
        #pragma unroll
        for (int q = 0; q < 2; ++q) {
            const int row = brow + q * 16;
            const float* src = wt + ((size_t)(tap * 128 + csub * 32 + row) * CCOUT
                                     + bn * BN) + bsc * 4;
            const uint32_t dst = b_st + (uint32_t)row * (B_ROW * 4) + bsc * 16;
            cp16(dst, src, 16u);
        }
        CP_COMMIT();
    };

    // prologue: stages 0,1
    load_chunk(0, 0);
    load_chunk(1, 1);

    for (int i = 0; i < NCHUNKS; ++i) {
        CP_WAIT1();
        __syncthreads();

        // issue next load (into the stage whose readers finished before this sync)
        if (i + 2 < NCHUNKS) load_chunk(i + 2, (i + 2) % STAGES);
        else CP_COMMIT();   // keep group accounting uniform

        // ---- compute on stage i%STAGES ----
        const int stage = i % STAGES;
        const float* As = smem + stage * A_STAGE_W + warp_m * 64 * A_ROW;
        const float* Bs = smem + STAGES * A_STAGE_W + stage * B_STAGE_W
                        + warp_n * 32;

        #pragma unroll
        for (int j = 0; j < 4; ++j) {
            const int k0 = j * 8 + lc;
            uint32_t a[4][4], b[4][2];
            #pragma unroll
            for (int t = 0; t < 4; ++t) {
                const float* ap = As + (t * 16 + lr) * A_ROW + k0;
                a[t][0] = __float_as_uint(ap[0]);
                a[t][1] = __float_as_uint(ap[8 * A_ROW]);
                a[t][2] = __float_as_uint(ap[4]);
                a[t][3] = __float_as_uint(ap[8 * A_ROW + 4]);
            }
            #pragma unroll
            for (int u = 0; u < 4; ++u) {
                const float* bp = Bs + k0 * B_ROW + u * 8 + lr;
                b[u][0] = __float_as_uint(bp[0]);
                b[u][1] = __float_as_uint(bp[4 * B_ROW]);
            }
            #pragma unroll
            for (int t = 0; t < 4; ++t)
                #pragma unroll
                for (int u = 0; u < 4; ++u)
                    mma_tf32(acc[t][u], a[t], b[u]);
        }
    }

    // ---------------- epilogue: bias + store ----------------
    float bv0[4], bv1[4];
    #pragma unroll
    for (int u = 0; u < 4; ++u) {
        const int c = bn * BN + warp_n * 32 + u * 8 + lc * 2;
        bv0[u] = bias[c];
        bv1[u] = bias[c + 1];
    }
    #pragma unroll
    for (int t = 0; t < 4; ++t) {
        const int r0 = bm * BM + warp_m * 64 + t * 16 + lr;
        #pragma unroll
        for (int u = 0; u < 4; ++u) {
            const int c = bn * BN + warp_n * 32 + u * 8 + lc * 2;
            float2 v0 = make_float2(acc[t][u][0] + bv0[u], acc[t][u][1] + bv1[u]);
            float2 v1 = make_float2(acc[t][u][2] + bv0[u], acc[t][u][3] + bv1[u]);
            *(float2*)(out + (size_t)r0 * CCOUT + c)       = v0;
            *(float2*)(out + (size_t)(r0 + 8) * CCOUT + c) = v1;
        }
    }
}

// ---------------- host launch ----------------
extern "C" void kernel_launch(void* const* d_in, const int* in_sizes, int n_in,
                              void* d_out, int out_size)
{
    const float* x    = (const float*)d_in[0];
    const float* w    = (const float*)d_in[1];
    const float* bias = (const float*)d_in[2];
    float* out = (float*)d_out;

    float *gx = nullptr, *gw = nullptr;
    cudaGetSymbolAddress((void**)&gx, g_x_t);
    cudaGetSymbolAddress((void**)&gw, g_w_t);

    // pre-passes: round both operands to tf32 (rne) once
    k_cvt<<<2048, 256>>>(x, gx, NPIX * CCIN / 4);
    k_cvt<<<288, 256>>>(w, gw, KTOT * CCOUT / 4);

    cudaFuncSetAttribute(conv_mma, cudaFuncAttributeMaxDynamicSharedMemorySize,
                         SMEM_BYTES);
    dim3 grid(CCOUT / BN, NPIX / BM);   // (2, 392)
    conv_mma<<<grid, NTHREADS, SMEM_BYTES>>>(gx, gw, bias, out);
}